// round 1
// baseline (speedup 1.0000x reference)
#include <cuda_runtime.h>
#include <math.h>

#define BATCH   16
#define LSEQ    2048
#define DMODEL  256
#define DINNER  512
#define DSTATE  16
#define NOUT    256
#define NROWS   (BATCH*LSEQ)   /* 32768 */

// ---------------- device scratch (no allocations allowed) ----------------
__device__ float  g_xz[(size_t)NROWS * 1024];        // in_proj output (x | z)
__device__ float4 g_scanin[(size_t)NROWS * DINNER];  // (delta, xc, silu(z), xc*D)
__device__ float2 g_bc[(size_t)NROWS * DSTATE];      // (B_n, C_n)
__device__ float  g_y[(size_t)NROWS * DINNER];       // scan output (pre out_proj)
__device__ float  g_t1[(size_t)NROWS * NOUT];        // silu(out_proj)
__device__ float  g_psum[512 * 2];                   // per-block (sum, sumsq)
__device__ float2 g_stats[BATCH];                    // (mean, rstd)

__device__ __forceinline__ float silu_f(float v) {
    return v / (1.f + __expf(-v));
}

// ---------------- generic NT SGEMM: C[M,N] = A[M,K] * B[N,K]^T -----------
// BM=BN=128, BK=8, 256 threads, 8x8 per thread. All dims are multiples of
// the tile sizes for every call in this problem, so no bounds checks.
// EPI: 0 = plain, 1 = silu, 2 = +bias, write, and per-block (sum,sumsq) -> g_psum
template <int EPI>
__global__ void __launch_bounds__(256)
gemm_nt_kernel(const float* __restrict__ A, const float* __restrict__ B,
               float* __restrict__ C, int M, int N, int K,
               const float* __restrict__ bias)
{
    __shared__ float As[8][128];
    __shared__ float Bs[8][128];
    __shared__ float rs[256];
    __shared__ float rss[256];

    const int tid = threadIdx.x;
    const int bm = blockIdx.y, bn = blockIdx.x;

    const int lrow = tid >> 1;          // 0..127
    const int lcol = (tid & 1) * 4;     // 0 or 4
    const float* Ag = A + (size_t)(bm * 128 + lrow) * K + lcol;
    const float* Bg = B + (size_t)(bn * 128 + lrow) * K + lcol;

    const int tm = (tid >> 4) * 8;
    const int tn = (tid & 15) * 8;

    float c[8][8] = {};

    const int nk = K / 8;
    for (int kt = 0; kt < nk; ++kt) {
        float4 av = *(const float4*)(Ag + kt * 8);
        float4 bv = *(const float4*)(Bg + kt * 8);
        As[lcol + 0][lrow] = av.x; As[lcol + 1][lrow] = av.y;
        As[lcol + 2][lrow] = av.z; As[lcol + 3][lrow] = av.w;
        Bs[lcol + 0][lrow] = bv.x; Bs[lcol + 1][lrow] = bv.y;
        Bs[lcol + 2][lrow] = bv.z; Bs[lcol + 3][lrow] = bv.w;
        __syncthreads();
#pragma unroll
        for (int k = 0; k < 8; ++k) {
            float4 a0 = *(const float4*)&As[k][tm];
            float4 a1 = *(const float4*)&As[k][tm + 4];
            float4 b0 = *(const float4*)&Bs[k][tn];
            float4 b1 = *(const float4*)&Bs[k][tn + 4];
            float a[8] = {a0.x,a0.y,a0.z,a0.w,a1.x,a1.y,a1.z,a1.w};
            float b[8] = {b0.x,b0.y,b0.z,b0.w,b1.x,b1.y,b1.z,b1.w};
#pragma unroll
            for (int i = 0; i < 8; ++i)
#pragma unroll
                for (int j = 0; j < 8; ++j)
                    c[i][j] = fmaf(a[i], b[j], c[i][j]);
        }
        __syncthreads();
    }

    float s = 0.f, ss = 0.f;
#pragma unroll
    for (int i = 0; i < 8; ++i) {
        float* Crow = C + (size_t)(bm * 128 + tm + i) * N + bn * 128 + tn;
#pragma unroll
        for (int j = 0; j < 8; j += 4) {
            float v[4];
#pragma unroll
            for (int q = 0; q < 4; ++q) {
                float x = c[i][j + q];
                if (EPI == 1) x = silu_f(x);
                if (EPI == 2) {
                    x += bias[bn * 128 + tn + j + q];
                    s += x; ss += x * x;
                }
                v[q] = x;
            }
            *(float4*)(Crow + j) = make_float4(v[0], v[1], v[2], v[3]);
        }
    }

    if (EPI == 2) {
        rs[tid] = s; rss[tid] = ss;
        __syncthreads();
        for (int off = 128; off > 0; off >>= 1) {
            if (tid < off) { rs[tid] += rs[tid + off]; rss[tid] += rss[tid + off]; }
            __syncthreads();
        }
        if (tid == 0) {
            int pid = bm * gridDim.x + bn;
            g_psum[2 * pid] = rs[0];
            g_psum[2 * pid + 1] = rss[0];
        }
    }
}

// ---------- fused causal conv + SiLU + x_proj + dt_proj + pack -----------
// one block per token-row, 512 threads (one per inner channel)
__global__ void __launch_bounds__(512)
convproj_kernel(const float* __restrict__ conv_w, const float* __restrict__ conv_b,
                const float* __restrict__ x_proj_w, const float* __restrict__ dt_proj_w,
                const float* __restrict__ dt_proj_b, const float* __restrict__ D_skip)
{
    const int row = blockIdx.x;
    const int b = row >> 11;
    const int l = row & 2047;
    const int d = threadIdx.x;

    __shared__ float xc_s[512];
    __shared__ float xdbl_s[48];

    // causal depthwise conv (D_CONV=4) over x = xz[:, 0:512]
    float4 cw = ((const float4*)conv_w)[d];
    float acc = conv_b[d];
    const float* xbase = g_xz + (size_t)(b * 2048) * 1024 + d;
    if (l >= 3) {
        acc += xbase[(size_t)(l - 3) * 1024] * cw.x
             + xbase[(size_t)(l - 2) * 1024] * cw.y
             + xbase[(size_t)(l - 1) * 1024] * cw.z
             + xbase[(size_t)(l    ) * 1024] * cw.w;
    } else {
        const float* cwp = (const float*)&cw;
#pragma unroll
        for (int k = 0; k < 4; ++k) {
            int ls = l + k - 3;
            if (ls >= 0) acc += xbase[(size_t)ls * 1024] * cwp[k];
        }
    }
    float xc = silu_f(acc);
    xc_s[d] = xc;
    __syncthreads();

    // x_dbl[48] = xc . x_proj_w^T  (16 warps x 3 outputs, warp-cooperative)
    const int warp = d >> 5, lane = d & 31;
#pragma unroll
    for (int jj = 0; jj < 3; ++jj) {
        int j = warp * 3 + jj;
        const float* wrow = x_proj_w + j * 512;
        float a = 0.f;
#pragma unroll
        for (int it = 0; it < 16; ++it) {
            int dd = lane + it * 32;
            a = fmaf(xc_s[dd], wrow[dd], a);
        }
#pragma unroll
        for (int off = 16; off; off >>= 1)
            a += __shfl_xor_sync(0xffffffffu, a, off);
        if (lane == 0) xdbl_s[j] = a;
    }
    __syncthreads();

    // delta = softplus(dt @ dt_proj_w^T + b)
    float dt = dt_proj_b[d];
    const float4* dw = (const float4*)(dt_proj_w + d * 16);
#pragma unroll
    for (int q = 0; q < 4; ++q) {
        float4 w4 = dw[q];
        dt = fmaf(xdbl_s[4*q+0], w4.x, dt);
        dt = fmaf(xdbl_s[4*q+1], w4.y, dt);
        dt = fmaf(xdbl_s[4*q+2], w4.z, dt);
        dt = fmaf(xdbl_s[4*q+3], w4.w, dt);
    }
    float delta = (dt > 20.f) ? dt : log1pf(__expf(dt));

    float z = g_xz[(size_t)row * 1024 + 512 + d];
    g_scanin[(size_t)row * 512 + d] =
        make_float4(delta, xc, silu_f(z), xc * D_skip[d]);

    if (d < 16)
        g_bc[(size_t)row * 16 + d] = make_float2(xdbl_s[16 + d], xdbl_s[32 + d]);
}

// ---------------------- diagonal selective scan ---------------------------
// warp handles 2 (b,d) lanes: lanes 0-15 -> d0 states, 16-31 -> d1 states.
// h kept in a register; y reduced over 16 states via shfl_xor (off critical path).
__global__ void __launch_bounds__(256)
scan_kernel(const float* __restrict__ A_log)
{
    const int blk = blockIdx.x;
    const int b = blk >> 5;
    const int dbase = (blk & 31) * 16;
    const int warp = threadIdx.x >> 5, lane = threadIdx.x & 31;
    const int half = lane >> 4, n = lane & 15;
    const int d = dbase + warp * 2 + half;

    const float An = -__expf(A_log[d * 16 + n]);   // = -(n+1)
    const float4* sp = g_scanin + (size_t)b * 2048 * 512 + d;
    const float2* bp = g_bc + (size_t)b * 2048 * 16 + n;
    float* yp = g_y + (size_t)b * 2048 * 512 + d;

    float h = 0.f;
#pragma unroll 4
    for (int t = 0; t < 2048; ++t) {
        float4 v = sp[(size_t)t * 512];   // broadcast within half-warp
        float2 w = bp[(size_t)t * 16];
        float dA = __expf(v.x * An);
        h = fmaf(dA, h, v.x * v.y * w.x);
        float p = h * w.y;
        p += __shfl_xor_sync(0xffffffffu, p, 8);
        p += __shfl_xor_sync(0xffffffffu, p, 4);
        p += __shfl_xor_sync(0xffffffffu, p, 2);
        p += __shfl_xor_sync(0xffffffffu, p, 1);
        if (n == 0)
            yp[(size_t)t * 512] = (p + v.w) * v.z;  // (y + xc*D) * silu(z)
    }
}

// ------------------------- LayerNorm stats + apply ------------------------
__global__ void stats_kernel()
{
    int b = threadIdx.x;
    if (b >= BATCH) return;
    double s = 0.0, ss = 0.0;
    for (int bm = b * 16; bm < b * 16 + 16; ++bm)
        for (int bn = 0; bn < 2; ++bn) {
            int pid = bm * 2 + bn;
            s  += (double)g_psum[2 * pid];
            ss += (double)g_psum[2 * pid + 1];
        }
    const double nd = (double)LSEQ * NOUT;
    double mu = s / nd;
    double var = ss / nd - mu * mu;
    g_stats[b] = make_float2((float)mu, (float)rsqrt(var + 1e-5));
}

__global__ void __launch_bounds__(256)
norm_kernel(float* __restrict__ out, const float* __restrict__ lnw,
            const float* __restrict__ lnb)
{
    size_t i4 = (size_t)blockIdx.x * 256 + threadIdx.x;
    size_t base = i4 * 4;
    int row = (int)(base >> 8);
    int b = row >> 11;
    int l = row & 2047;
    int o = (int)(base & 255);
    float2 st = g_stats[b];
    float4 v = *(float4*)(out + base);
    const float4 w  = *(const float4*)(lnw + (size_t)l * 256 + o);
    const float4 bb = *(const float4*)(lnb + (size_t)l * 256 + o);
    v.x = (v.x - st.x) * st.y * w.x + bb.x;
    v.y = (v.y - st.x) * st.y * w.y + bb.y;
    v.z = (v.z - st.x) * st.y * w.z + bb.z;
    v.w = (v.w - st.x) * st.y * w.w + bb.w;
    *(float4*)(out + base) = v;
}

// ------------------------------- launch -----------------------------------
extern "C" void kernel_launch(void* const* d_in, const int* in_sizes, int n_in,
                              void* d_out, int out_size)
{
    const float* inputs    = (const float*)d_in[0];
    const float* in_proj_w = (const float*)d_in[1];
    const float* conv_w    = (const float*)d_in[2];
    const float* conv_b    = (const float*)d_in[3];
    const float* x_proj_w  = (const float*)d_in[4];
    const float* dt_proj_w = (const float*)d_in[5];
    const float* dt_proj_b = (const float*)d_in[6];
    const float* A_log     = (const float*)d_in[7];
    const float* D_skip    = (const float*)d_in[8];
    const float* out_proj_w= (const float*)d_in[9];
    const float* dim_w     = (const float*)d_in[10];
    const float* dim_b     = (const float*)d_in[11];
    const float* ln_w      = (const float*)d_in[12];
    const float* ln_b      = (const float*)d_in[13];
    float* out = (float*)d_out;

    float *xz, *y, *t1;
    cudaGetSymbolAddress((void**)&xz, g_xz);
    cudaGetSymbolAddress((void**)&y,  g_y);
    cudaGetSymbolAddress((void**)&t1, g_t1);

    // 1) xz = inputs @ in_proj_w^T   [32768 x 1024]
    gemm_nt_kernel<0><<<dim3(1024 / 128, NROWS / 128), 256>>>(
        inputs, in_proj_w, xz, NROWS, 1024, 256, nullptr);

    // 2) conv + silu + x_proj + dt_proj, packed scan inputs
    convproj_kernel<<<NROWS, 512>>>(conv_w, conv_b, x_proj_w,
                                    dt_proj_w, dt_proj_b, D_skip);

    // 3) selective scan (+D skip, * silu(z))
    scan_kernel<<<512, 256>>>(A_log);

    // 4) t1 = silu(y @ out_proj_w^T)  [32768 x 256]
    gemm_nt_kernel<1><<<dim3(256 / 128, NROWS / 128), 256>>>(
        y, out_proj_w, t1, NROWS, 256, 512, nullptr);

    // 5) out = t1 @ dim_w^T + dim_b, plus per-block partial sums
    gemm_nt_kernel<2><<<dim3(256 / 128, NROWS / 128), 256>>>(
        t1, dim_w, out, NROWS, 256, 256, dim_b);

    // 6) per-batch LayerNorm over (L, N_OUT)
    stats_kernel<<<1, 32>>>();
    norm_kernel<<<(NROWS * NOUT / 4) / 256, 256>>>(out, ln_w, ln_b);
}